// round 15
// baseline (speedup 1.0000x reference)
#include <cuda_runtime.h>
#include <cuda_bf16.h>
#include <math.h>
#include <stdint.h>

// ---------------------------------------------------------------------------
// Problem constants
// ---------------------------------------------------------------------------
#define BB 4
#define NN 16384
#define CC 128
#define MM 1024
#define KK 32
#define RROWS (BB*MM*KK)        // 131072
#define COUT1 128
#define COUT2 128
#define COUT3 256
#define NBLK (RROWS/128)        // 1024 row-tiles
#define NGRP (BB*MM)            // 4096
#define OUT_XYZ_ELEMS (BB*MM*3) // 12288
#define SEGB 4096               // one W segment: 128 rows x 32B
#define SROW 136                // A-stage row stride in floats (136 % 32 == 8)
#define STAGEF (8*16*SROW)      // one stage buffer: 8 wm-groups x 16 rows

// ---------------------------------------------------------------------------
// Scratch (static device globals)
// ---------------------------------------------------------------------------
__device__ float g_featT[(size_t)BB*NN*CC];          // 32 MB (B,N,C)
__device__ int   g_idx[(size_t)BB*MM*KK];            // 512 KB
__device__ float g_Y1[(size_t)RROWS*COUT1];          // 64 MB
__device__ float g_Y2[(size_t)RROWS*COUT2];          // 64 MB
__device__ float g_gmax[(size_t)2*NGRP*COUT3];       // 8 MB (per-16-row halves)
__device__ unsigned char g_w1s[18*SEGB];             // 9 chunks x {hi,lo} segs
__device__ unsigned char g_w2s[16*SEGB];
__device__ unsigned char g_w3s[2*16*SEGB];           // 2 col-tiles
__device__ float g_part[(size_t)8*NBLK*2*COUT3];     // per (tile, wm) partials
__device__ float g_bn[6*COUT3];

// ---------------------------------------------------------------------------
// helpers
// ---------------------------------------------------------------------------
__device__ __forceinline__ uint32_t smem_u32(const void* p) {
    uint32_t a;
    asm("{ .reg .u64 t; cvta.to.shared.u64 t, %1; cvt.u32.u64 %0, t; }"
        : "=r"(a) : "l"(p));
    return a;
}
__device__ __forceinline__ void ldm_x4(uint32_t* r, uint32_t addr) {
    asm volatile("ldmatrix.sync.aligned.m8n8.x4.shared.b16 {%0,%1,%2,%3}, [%4];"
        : "=r"(r[0]), "=r"(r[1]), "=r"(r[2]), "=r"(r[3]) : "r"(addr));
}
__device__ __forceinline__ void mma16816(float* c,
        const uint32_t* a, uint32_t b0, uint32_t b1) {
    asm volatile(
        "mma.sync.aligned.m16n8k16.row.col.f32.bf16.bf16.f32 "
        "{%0,%1,%2,%3}, {%4,%5,%6,%7}, {%8,%9}, {%0,%1,%2,%3};\n"
        : "+f"(c[0]), "+f"(c[1]), "+f"(c[2]), "+f"(c[3])
        : "r"(a[0]), "r"(a[1]), "r"(a[2]), "r"(a[3]), "r"(b0), "r"(b1));
}
// round-to-nearest bf16 hi/lo split of a float2, packed as bf16x2 words
__device__ __forceinline__ void split2(float2 v, uint32_t& hi, uint32_t& lo) {
    uint32_t t0 = __float_as_uint(v.x) + 0x8000u;
    uint32_t t1 = __float_as_uint(v.y) + 0x8000u;
    float h0 = __uint_as_float(t0 & 0xFFFF0000u);
    float h1 = __uint_as_float(t1 & 0xFFFF0000u);
    hi = __byte_perm(t0, t1, 0x7632);
    uint32_t l0 = __float_as_uint(v.x - h0) + 0x8000u;
    uint32_t l1 = __float_as_uint(v.y - h1) + 0x8000u;
    lo = __byte_perm(l0, l1, 0x7632);
}
#define CP_ASYNC16(dst, src) \
    asm volatile("cp.async.cg.shared.global [%0], [%1], 16;" :: "r"(dst), "l"(src))
#define CP_COMMIT() asm volatile("cp.async.commit_group;" ::: "memory")
#define CP_WAIT0()  asm volatile("cp.async.wait_group 0;" ::: "memory")
#define BAR_PAIR(id) asm volatile("bar.sync %0, 64;" :: "r"(id) : "memory")

// ---------------------------------------------------------------------------
// 1) transpose features (B,C,N) -> (B,N,C).  256 thr, float4 both directions.
// ---------------------------------------------------------------------------
__global__ void transpose_feat_kernel(const float* __restrict__ f) {
    __shared__ __align__(16) float tile[32][132];
    int b  = blockIdx.z;
    int n0 = blockIdx.x * 128;
    int c0 = blockIdx.y * 32;
    int tx = threadIdx.x, ty = threadIdx.y;   // (32, 8)
    #pragma unroll
    for (int i = 0; i < 4; i++) {
        int c = ty*4 + i;
        float4 v = *(const float4*)(f + ((size_t)b*CC + c0 + c)*NN + n0 + tx*4);
        *(float4*)&tile[c][tx*4] = v;
    }
    __syncthreads();
    int t = ty*32 + tx;
    int n = t & 127, cg = t >> 7;
    #pragma unroll
    for (int i = 0; i < 4; i++) {
        int c = cg*16 + i*4;
        float4 v = make_float4(tile[c][n], tile[c+1][n], tile[c+2][n], tile[c+3][n]);
        *(float4*)(g_featT + ((size_t)b*NN + n0 + n)*CC + c0 + c) = v;
    }
}

// ---------------------------------------------------------------------------
// 2) ball query: warp per query, 64 points/iteration (2 per lane).
// ---------------------------------------------------------------------------
__global__ void ballquery_kernel(const float* __restrict__ xyz,
                                 const int*   __restrict__ indices,
                                 float*       __restrict__ out_newxyz) {
    int gw   = (blockIdx.x * blockDim.x + threadIdx.x) >> 5;
    int lane = threadIdx.x & 31;
    if (gw >= BB*MM) return;
    int b = gw >> 10;
    const float R2 = (float)(0.4 * 0.4);
    const float* base = xyz + (size_t)b*NN*3;
    int ctr = indices[gw];
    float cx = base[ctr*3+0], cy = base[ctr*3+1], cz = base[ctr*3+2];
    if (lane < 3) out_newxyz[gw*3 + lane] = base[ctr*3+lane];

    unsigned lt = (1u << lane) - 1u;
    int cnt = 0, first = 0;
    int* myidx = g_idx + (size_t)gw*KK;
    for (int j0 = 0; j0 < NN; j0 += 64) {
        int ja = j0 + lane, jb = j0 + 32 + lane;
        float dxa = base[ja*3+0]-cx, dya = base[ja*3+1]-cy, dza = base[ja*3+2]-cz;
        float dxb = base[jb*3+0]-cx, dyb = base[jb*3+1]-cy, dzb = base[jb*3+2]-cz;
        bool wa = (dxa*dxa + dya*dya + dza*dza) < R2;
        bool wb = (dxb*dxb + dyb*dyb + dzb*dzb) < R2;
        unsigned m1 = __ballot_sync(0xffffffffu, wa);
        unsigned m2 = __ballot_sync(0xffffffffu, wb);
        if (m1 | m2) {
            if (cnt == 0)
                first = m1 ? (j0 + __ffs(m1) - 1) : (j0 + 32 + __ffs(m2) - 1);
            int c1 = __popc(m1);
            int p1 = __popc(m1 & lt);
            if (wa && (cnt + p1) < KK) myidx[cnt + p1] = ja;
            int p2 = __popc(m2 & lt);
            if (wb && (cnt + c1 + p2) < KK) myidx[cnt + c1 + p2] = jb;
            cnt += c1 + __popc(m2);
            if (cnt >= KK) break;
        }
    }
    int ce = cnt < KK ? cnt : KK;
    if (lane >= ce) myidx[lane] = first;
}

// ---------------------------------------------------------------------------
// 3) weight split into per-segment smem image:
//    layout per col-tile: [chunk c][seg 0=hi,1=lo][n(128)][16 bf16]
//    perm=1 (layer1): k<128 -> w[:,3+k]; 128..130 -> w[:,k-128]; else 0
// ---------------------------------------------------------------------------
__global__ void splitw_kernel(const float* __restrict__ w,
                              unsigned char* __restrict__ out,
                              int Cin, int nSeg, int perm) {
    int o = blockIdx.x, k = threadIdx.x;
    int wt = o >> 7, n = o & 127;
    float v;
    if (perm) {
        if (k < 128)      v = w[o*Cin + 3 + k];
        else if (k < 131) v = w[o*Cin + (k - 128)];
        else              v = 0.f;
    } else {
        v = (k < Cin) ? w[o*Cin + k] : 0.f;
    }
    __nv_bfloat16 h = __float2bfloat16_rn(v);
    __nv_bfloat16 l = __float2bfloat16_rn(v - __bfloat162float(h));
    int c = k >> 4, kk = k & 15;
    unsigned char* base = out + (size_t)wt * nSeg * SEGB;
    *(__nv_bfloat16*)(base + ((size_t)(2*c+0)*128 + n)*32 + kk*2) = h;
    *(__nv_bfloat16*)(base + ((size_t)(2*c+1)*128 + n)*32 + kk*2) = l;
}

// ---------------------------------------------------------------------------
// Persistent fused GEMM, smem-staged A, 16 warps.
//   MODE 0: A = virtual gathered X1 (featT + dxyz), K=144 (9 chunks) -> Y1
//   MODE 1: A = Y1, act=relu(bn).  K=128.                            -> Y2
//   MODE 2: A = Y2, act=relu(bn).  stats + half-K-group max, no Y.
// Block 128x128, 512 thr (16 warps: wm 0..7 x wn 0..1), warp tile 16x64.
// Same total work as the 8-warp version, but 4 warps/SMSP for latency hiding.
// A rows cp.async-staged whole-K (coalesced, double-buffered); fragments read
// as LDS.64 (stride 136); BN/ReLU + integer hi/lo split in registers.
// NO __syncthreads in the tile loop -- per-wm named barrier (2 warps, 64 thr).
// Split precision: A,W {hi,lo}; products hi*hi + hi*lo + lo*hi.
// ---------------------------------------------------------------------------
template<int MODE>
__global__ __launch_bounds__(512, 1)
void gemm_rr(const float* __restrict__ A,
             const unsigned char* __restrict__ Wt,
             const float* __restrict__ bias,
             const float* __restrict__ bn_a, const float* __restrict__ bn_c,
             float* __restrict__ Y,
             const float* __restrict__ xyz, const float* __restrict__ newxyz) {
    constexpr int NCH   = (MODE == 0) ? 9 : 8;
    constexpr int NSEG  = 2 * NCH;
    constexpr int COUTT = (MODE == 2) ? 256 : 128;

    extern __shared__ unsigned char dsm[];
    unsigned char* Wsm = dsm;                        // NSEG*SEGB
    float* smA = (float*)(dsm + NSEG*SEGB);          // 2 * STAGEF floats

    __shared__ float s_bias[128];
    __shared__ float s_bna[128], s_bnc[128];

    int tid  = threadIdx.x;
    int lane = tid & 31, warp = tid >> 5;   // warp 0..15
    int wm = warp >> 1, wn = warp & 1;      // wm 0..7
    int colTile = blockIdx.y * 128;
    int gg = lane >> 2, tq = lane & 3;

    uint32_t wsm_a = smem_u32(Wsm);

    if (tid < 128) {
        s_bias[tid] = bias[colTile + tid];
        if (MODE != 0) { s_bna[tid] = bn_a[tid]; s_bnc[tid] = bn_c[tid]; }
    }
    // W tile -> smem (once per CTA)
    {
        const unsigned char* wsrc = Wt + (size_t)blockIdx.y * NSEG * SEGB;
        for (int i = tid; i < NSEG*256; i += 512)
            CP_ASYNC16(wsm_a + i*16, wsrc + (size_t)i*16);
        CP_COMMIT();
    }

    // ---- A stage prefetch: this warp stages 8 of its pair's 16 rows,
    //      whole K (128 floats), one coalesced cp.async row per instruction
    uint32_t smA_a = smem_u32(smA);
    auto prefetch = [&](int t, int buf) {
        if (t < NBLK) {
            #pragma unroll
            for (int i = 0; i < 8; i++) {
                int r  = wn*8 + i;                   // row within 16-row group
                int rg = t*128 + wm*16 + r;
                const float* src;
                if (MODE == 0) {
                    int jj = g_idx[rg];
                    int bb = rg >> 15;
                    src = g_featT + ((size_t)bb*NN + jj)*CC;
                } else {
                    src = A + (size_t)rg*128;
                }
                uint32_t dst = smA_a +
                    (uint32_t)(((buf*8 + wm)*16 + r)*SROW + lane*4)*4;
                CP_ASYNC16(dst, src + lane*4);
            }
        }
        CP_COMMIT();
    };

    prefetch(blockIdx.x, 0);
    CP_WAIT0();
    __syncthreads();          // once: W + first stage visible to everyone

    uint32_t boff = (uint32_t)((wn*64 + (lane & 7) + ((lane >> 4) & 1)*8)*32
                               + ((lane >> 3) & 1)*16);
    int buf = 0;

    for (int t = blockIdx.x; t < NBLK; t += gridDim.x) {
        // prefetch next tile into the other buffer (overlaps this compute)
        prefetch(t + gridDim.x, buf ^ 1);

        // ---- per-tile dxyz (MODE 0 only, fragment-resident)
        float dxr[2], dyr[2], dzr[2];
        if (MODE == 0) {
            #pragma unroll
            for (int h = 0; h < 2; h++) {
                int rg = t*128 + wm*16 + h*8 + gg;
                int jj = g_idx[rg];
                int bb = rg >> 15;
                const float* pp = xyz    + ((size_t)bb*NN + jj)*3;
                const float* cq = newxyz + (size_t)(rg >> 5)*3;
                dxr[h] = pp[0]-cq[0];
                dyr[h] = pp[1]-cq[1];
                dzr[h] = pp[2]-cq[2];
            }
        }

        // fragment-row base offsets in the stage (floats)
        const float* arow[2];
        #pragma unroll
        for (int h = 0; h < 2; h++)
            arow[h] = smA + (size_t)(((buf*8 + wm)*16 + h*8 + gg)*SROW + 2*tq);

        float acc[8][4];
        #pragma unroll
        for (int nf = 0; nf < 8; nf++)
            #pragma unroll
            for (int r2 = 0; r2 < 4; r2++) acc[nf][r2] = 0.f;

        #pragma unroll
        for (int c = 0; c < NCH; c++) {
            // ---- build A fragments from the smem stage ----
            uint32_t ah[4], al[4];
            if (MODE == 0 && c == 8) {
                #pragma unroll
                for (int h = 0; h < 2; h++) {
                    float2 v;   // cols 128+2tq, 129+2tq
                    v.x = (tq == 0) ? dxr[h] : (tq == 1) ? dzr[h] : 0.f;
                    v.y = (tq == 0) ? dyr[h] : 0.f;
                    split2(v, ah[h], al[h]);
                }
                ah[2] = 0u; al[2] = 0u;   // cols >= 136: zero
                ah[3] = 0u; al[3] = 0u;
            } else {
                float2 ba0, bc0, ba8, bc8;
                if (MODE != 0) {
                    ba0 = *(const float2*)&s_bna[c*16 + 2*tq];
                    bc0 = *(const float2*)&s_bnc[c*16 + 2*tq];
                    ba8 = *(const float2*)&s_bna[c*16 + 2*tq + 8];
                    bc8 = *(const float2*)&s_bnc[c*16 + 2*tq + 8];
                }
                #pragma unroll
                for (int h = 0; h < 2; h++) {
                    float2 v0 = *(const float2*)(arow[h] + c*16);
                    float2 v8 = *(const float2*)(arow[h] + c*16 + 8);
                    if (MODE != 0) {
                        v0.x = fmaxf(fmaf(v0.x, ba0.x, bc0.x), 0.f);
                        v0.y = fmaxf(fmaf(v0.y, ba0.y, bc0.y), 0.f);
                        v8.x = fmaxf(fmaf(v8.x, ba8.x, bc8.x), 0.f);
                        v8.y = fmaxf(fmaf(v8.y, ba8.y, bc8.y), 0.f);
                    }
                    split2(v0, ah[h],     al[h]);      // reg h   (k0)
                    split2(v8, ah[2 + h], al[2 + h]);  // reg 2+h (k8)
                }
            }

            // ---- B fragments from smem ----
            uint32_t bh[8][2], bl[8][2];
            #pragma unroll
            for (int j = 0; j < 4; j++) {
                uint32_t r4[4];
                ldm_x4(r4, wsm_a + (uint32_t)(2*c)*SEGB + boff + j*512);
                bh[2*j][0] = r4[0]; bh[2*j][1] = r4[1];
                bh[2*j+1][0] = r4[2]; bh[2*j+1][1] = r4[3];
                ldm_x4(r4, wsm_a + (uint32_t)(2*c+1)*SEGB + boff + j*512);
                bl[2*j][0] = r4[0]; bl[2*j][1] = r4[1];
                bl[2*j+1][0] = r4[2]; bl[2*j+1][1] = r4[3];
            }
            #pragma unroll
            for (int nf = 0; nf < 8; nf++) {
                mma16816(acc[nf], ah, bh[nf][0], bh[nf][1]);
                mma16816(acc[nf], ah, bl[nf][0], bl[nf][1]);
                mma16816(acc[nf], al, bh[nf][0], bh[nf][1]);
            }
        }

        // ---- epilogue: bias, Y write, per-warp (16-row) stats/max ----
        float bs[8][2];
        #pragma unroll
        for (int nf = 0; nf < 8; nf++) {
            int col = wn*64 + nf*8 + 2*tq;
            bs[nf][0] = s_bias[col];
            bs[nf][1] = s_bias[col+1];
        }
        float s16[8][2], q16[8][2], m16[8][2];
        #pragma unroll
        for (int nf = 0; nf < 8; nf++) {
            float v0 = acc[nf][0] + bs[nf][0];
            float v1 = acc[nf][1] + bs[nf][1];
            float v2 = acc[nf][2] + bs[nf][0];
            float v3 = acc[nf][3] + bs[nf][1];
            s16[nf][0] = v0 + v2;  s16[nf][1] = v1 + v3;
            q16[nf][0] = fmaf(v0, v0, v2*v2);
            q16[nf][1] = fmaf(v1, v1, v3*v3);
            m16[nf][0] = fmaxf(v0, v2);
            m16[nf][1] = fmaxf(v1, v3);
            if (MODE != 2) {
                int r0 = t*128 + wm*16 + gg;
                int cb = colTile + wn*64 + nf*8 + 2*tq;
                *(float2*)(Y + (size_t)r0*COUTT + cb)     = make_float2(v0, v1);
                *(float2*)(Y + (size_t)(r0+8)*COUTT + cb) = make_float2(v2, v3);
            }
        }

        #pragma unroll
        for (int off = 4; off <= 16; off <<= 1) {
            #pragma unroll
            for (int nf = 0; nf < 8; nf++)
                #pragma unroll
                for (int e = 0; e < 2; e++) {
                    s16[nf][e] += __shfl_xor_sync(0xffffffffu, s16[nf][e], off);
                    q16[nf][e] += __shfl_xor_sync(0xffffffffu, q16[nf][e], off);
                    m16[nf][e] = fmaxf(m16[nf][e], __shfl_xor_sync(0xffffffffu, m16[nf][e], off));
                }
        }
        if (gg == 0) {
            size_t pb = (size_t)(t*8 + wm) * (2*COUTT);
            #pragma unroll
            for (int nf = 0; nf < 8; nf++)
                #pragma unroll
                for (int e = 0; e < 2; e++) {
                    int cl = wn*64 + nf*8 + 2*tq + e;
                    g_part[pb + colTile + cl]         = s16[nf][e];
                    g_part[pb + COUTT + colTile + cl] = q16[nf][e];
                    if (MODE == 2)   // half-group (16-row) max partial
                        g_gmax[((size_t)(t*8 + wm))*COUT3 + colTile + cl] = m16[nf][e];
                }
        }

        // ---- stage t+1 arrived (mine) + pair sibling done with this buffer
        CP_WAIT0();
        BAR_PAIR(wm + 1);
        buf ^= 1;
    }
}

// ---------------------------------------------------------------------------
// BN finalize: fixed-order reduce over 8*NBLK per-warp partials
// ---------------------------------------------------------------------------
__global__ void bn_finalize_kernel(int C,
                                   const float* __restrict__ g,
                                   const float* __restrict__ beta,
                                   float* __restrict__ bn_a,
                                   float* __restrict__ bn_c) {
    __shared__ float sh_s[256], sh_q[256];
    int ch = blockIdx.x;
    int t  = threadIdx.x;
    float s = 0.f, q = 0.f;
    for (int b = t; b < 8*NBLK; b += 256) {
        size_t base = (size_t)b * (2*C);
        s += g_part[base + ch];
        q += g_part[base + C + ch];
    }
    sh_s[t] = s; sh_q[t] = q;
    __syncthreads();
    for (int off = 128; off > 0; off >>= 1) {
        if (t < off) { sh_s[t] += sh_s[t+off]; sh_q[t] += sh_q[t+off]; }
        __syncthreads();
    }
    if (t == 0) {
        const float invR = 1.0f / (float)RROWS;
        float mu  = sh_s[0] * invR;
        float var = sh_q[0] * invR - mu*mu;
        float a = g[ch] * rsqrtf(var + 1e-5f);
        bn_a[ch] = a;
        bn_c[ch] = beta[ch] - a*mu;
    }
}

// ---------------------------------------------------------------------------
// Final: relu(a3*max(half0,half1) + c3) -> out
// (a3>0 so BN+relu commute with max over the K group)
// ---------------------------------------------------------------------------
__global__ void final_out_kernel(const float* __restrict__ bn_a,
                                 const float* __restrict__ bn_c,
                                 float* __restrict__ out) {
    int grp = blockIdx.x;
    int co  = threadIdx.x;
    float v = fmaxf(g_gmax[((size_t)(2*grp))*COUT3 + co],
                    g_gmax[((size_t)(2*grp+1))*COUT3 + co]);
    float r = fmaxf(fmaf(bn_a[co], v, bn_c[co]), 0.f);
    int b = grp >> 10, m = grp & 1023;
    out[OUT_XYZ_ELEMS + ((size_t)(b*COUT3 + co))*MM + m] = r;
}

// ---------------------------------------------------------------------------
// host launcher (gemm_rr<0> stays at launch index 3 for the ncu window)
// ---------------------------------------------------------------------------
extern "C" void kernel_launch(void* const* d_in, const int* in_sizes, int n_in,
                              void* d_out, int out_size) {
    const float* xyz     = (const float*)d_in[0];
    const float* feat    = (const float*)d_in[1];
    const int*   indices = (const int*)  d_in[2];
    const float* w1 = (const float*)d_in[3];
    const float* b1 = (const float*)d_in[4];
    const float* g1 = (const float*)d_in[5];
    const float* e1 = (const float*)d_in[6];
    const float* w2 = (const float*)d_in[7];
    const float* b2 = (const float*)d_in[8];
    const float* g2 = (const float*)d_in[9];
    const float* e2 = (const float*)d_in[10];
    const float* w3 = (const float*)d_in[11];
    const float* b3 = (const float*)d_in[12];
    const float* g3 = (const float*)d_in[13];
    const float* e3 = (const float*)d_in[14];
    float* out = (float*)d_out;

    float *Y1, *Y2, *bn;
    unsigned char *w1s, *w2s, *w3s;
    cudaGetSymbolAddress((void**)&Y1,  g_Y1);
    cudaGetSymbolAddress((void**)&Y2,  g_Y2);
    cudaGetSymbolAddress((void**)&bn,  g_bn);
    cudaGetSymbolAddress((void**)&w1s, g_w1s);
    cudaGetSymbolAddress((void**)&w2s, g_w2s);
    cudaGetSymbolAddress((void**)&w3s, g_w3s);
    float* a1 = bn;            float* c1 = bn + COUT3;
    float* a2 = bn + 2*COUT3;  float* c2 = bn + 3*COUT3;
    float* a3 = bn + 4*COUT3;  float* c3 = bn + 5*COUT3;

    int stageB = 2 * STAGEF * 4;              // 139264
    int smem1  = 18*SEGB + stageB;            // 212992
    int smem23 = 16*SEGB + stageB;            // 204800
    cudaFuncSetAttribute(gemm_rr<0>, cudaFuncAttributeMaxDynamicSharedMemorySize, smem1);
    cudaFuncSetAttribute(gemm_rr<1>, cudaFuncAttributeMaxDynamicSharedMemorySize, smem23);
    cudaFuncSetAttribute(gemm_rr<2>, cudaFuncAttributeMaxDynamicSharedMemorySize, smem23);

    // index 0..2: prep needed by gemm0
    splitw_kernel<<<COUT1, 144>>>(w1, w1s, 131, 18, 1);                     // 0
    {
        dim3 blk(32, 8);
        dim3 grd(NN/128, CC/32, BB);
        transpose_feat_kernel<<<grd, blk>>>(feat);                          // 1
    }
    ballquery_kernel<<<(BB*MM*32)/256, 256>>>(xyz, indices, out);           // 2

    // index 3: layer 1 GEMM (profiling target)
    gemm_rr<0><<<dim3(148,1), 512, smem1>>>(nullptr, w1s, b1, nullptr, nullptr,
                                            Y1, xyz, out);                  // 3
    bn_finalize_kernel<<<COUT1, 256>>>(COUT1, g1, e1, a1, c1);              // 4

    splitw_kernel<<<COUT2, 128>>>(w2, w2s, 128, 16, 0);                     // 5
    gemm_rr<1><<<dim3(148,1), 512, smem23>>>(Y1, w2s, b2, a1, c1,
                                             Y2, nullptr, nullptr);         // 6
    bn_finalize_kernel<<<COUT2, 256>>>(COUT2, g2, e2, a2, c2);              // 7

    splitw_kernel<<<COUT3, 128>>>(w3, w3s, 128, 16, 0);                     // 8
    gemm_rr<2><<<dim3(74,2), 512, smem23>>>(Y2, w3s, b3, a2, c2,
                                            nullptr, nullptr, nullptr);     // 9
    bn_finalize_kernel<<<COUT3, 256>>>(COUT3, g3, e3, a3, c3);              // 10

    final_out_kernel<<<NGRP, COUT3>>>(a3, c3, out);                         // 11
}

// round 16
// speedup vs baseline: 1.1739x; 1.1739x over previous
#include <cuda_runtime.h>
#include <cuda_bf16.h>
#include <math.h>
#include <stdint.h>

// ---------------------------------------------------------------------------
// Problem constants
// ---------------------------------------------------------------------------
#define BB 4
#define NN 16384
#define CC 128
#define MM 1024
#define KK 32
#define RROWS (BB*MM*KK)        // 131072
#define COUT1 128
#define COUT2 128
#define COUT3 256
#define NBLK (RROWS/128)        // 1024 row-tiles
#define NGRP (BB*MM)            // 4096
#define OUT_XYZ_ELEMS (BB*MM*3) // 12288
#define SEGB 4096               // one W segment: 128 rows x 32B
#define SROW 136                // A-stage row stride in floats (136 % 32 == 8)
#define STAGEF (4*32*SROW)      // one stage buffer (4 wm-groups x 32 rows)

// ---------------------------------------------------------------------------
// Scratch (static device globals)
// ---------------------------------------------------------------------------
__device__ float g_featT[(size_t)BB*NN*CC];          // 32 MB (B,N,C)
__device__ int   g_idx[(size_t)BB*MM*KK];            // 512 KB
__device__ float g_Y1[(size_t)RROWS*COUT1];          // 64 MB
__device__ float g_Y2[(size_t)RROWS*COUT2];          // 64 MB
__device__ float g_gmax[(size_t)NGRP*COUT3];         // 4 MB
__device__ unsigned char g_w1s[18*SEGB];             // 9 chunks x {hi,lo} segs
__device__ unsigned char g_w2s[16*SEGB];
__device__ unsigned char g_w3s[2*16*SEGB];           // 2 col-tiles
__device__ float g_part[(size_t)4*NBLK*2*COUT3];     // per (tile, wm) partials
__device__ float g_bn[6*COUT3];

// ---------------------------------------------------------------------------
// helpers
// ---------------------------------------------------------------------------
__device__ __forceinline__ uint32_t smem_u32(const void* p) {
    uint32_t a;
    asm("{ .reg .u64 t; cvta.to.shared.u64 t, %1; cvt.u32.u64 %0, t; }"
        : "=r"(a) : "l"(p));
    return a;
}
__device__ __forceinline__ void ldm_x4(uint32_t* r, uint32_t addr) {
    asm volatile("ldmatrix.sync.aligned.m8n8.x4.shared.b16 {%0,%1,%2,%3}, [%4];"
        : "=r"(r[0]), "=r"(r[1]), "=r"(r[2]), "=r"(r[3]) : "r"(addr));
}
__device__ __forceinline__ void mma16816(float* c,
        const uint32_t* a, uint32_t b0, uint32_t b1) {
    asm volatile(
        "mma.sync.aligned.m16n8k16.row.col.f32.bf16.bf16.f32 "
        "{%0,%1,%2,%3}, {%4,%5,%6,%7}, {%8,%9}, {%0,%1,%2,%3};\n"
        : "+f"(c[0]), "+f"(c[1]), "+f"(c[2]), "+f"(c[3])
        : "r"(a[0]), "r"(a[1]), "r"(a[2]), "r"(a[3]), "r"(b0), "r"(b1));
}
// round-to-nearest bf16 hi/lo split of a float2, packed as bf16x2 words
__device__ __forceinline__ void split2(float2 v, uint32_t& hi, uint32_t& lo) {
    uint32_t t0 = __float_as_uint(v.x) + 0x8000u;
    uint32_t t1 = __float_as_uint(v.y) + 0x8000u;
    float h0 = __uint_as_float(t0 & 0xFFFF0000u);
    float h1 = __uint_as_float(t1 & 0xFFFF0000u);
    hi = __byte_perm(t0, t1, 0x7632);
    uint32_t l0 = __float_as_uint(v.x - h0) + 0x8000u;
    uint32_t l1 = __float_as_uint(v.y - h1) + 0x8000u;
    lo = __byte_perm(l0, l1, 0x7632);
}
#define CP_ASYNC16(dst, src) \
    asm volatile("cp.async.cg.shared.global [%0], [%1], 16;" :: "r"(dst), "l"(src))
#define CP_COMMIT() asm volatile("cp.async.commit_group;" ::: "memory")
#define CP_WAIT0()  asm volatile("cp.async.wait_group 0;" ::: "memory")
#define BAR_PAIR(id) asm volatile("bar.sync %0, 64;" :: "r"(id) : "memory")

// ---------------------------------------------------------------------------
// 1) transpose features (B,C,N) -> (B,N,C).  256 thr, float4 both directions.
// ---------------------------------------------------------------------------
__global__ void transpose_feat_kernel(const float* __restrict__ f) {
    __shared__ __align__(16) float tile[32][132];
    int b  = blockIdx.z;
    int n0 = blockIdx.x * 128;
    int c0 = blockIdx.y * 32;
    int tx = threadIdx.x, ty = threadIdx.y;   // (32, 8)
    #pragma unroll
    for (int i = 0; i < 4; i++) {
        int c = ty*4 + i;
        float4 v = *(const float4*)(f + ((size_t)b*CC + c0 + c)*NN + n0 + tx*4);
        *(float4*)&tile[c][tx*4] = v;
    }
    __syncthreads();
    int t = ty*32 + tx;
    int n = t & 127, cg = t >> 7;
    #pragma unroll
    for (int i = 0; i < 4; i++) {
        int c = cg*16 + i*4;
        float4 v = make_float4(tile[c][n], tile[c+1][n], tile[c+2][n], tile[c+3][n]);
        *(float4*)(g_featT + ((size_t)b*NN + n0 + n)*CC + c0 + c) = v;
    }
}

// ---------------------------------------------------------------------------
// 2) ball query: warp per query, 64 points/iteration (2 per lane).
// ---------------------------------------------------------------------------
__global__ void ballquery_kernel(const float* __restrict__ xyz,
                                 const int*   __restrict__ indices,
                                 float*       __restrict__ out_newxyz) {
    int gw   = (blockIdx.x * blockDim.x + threadIdx.x) >> 5;
    int lane = threadIdx.x & 31;
    if (gw >= BB*MM) return;
    int b = gw >> 10;
    const float R2 = (float)(0.4 * 0.4);
    const float* base = xyz + (size_t)b*NN*3;
    int ctr = indices[gw];
    float cx = base[ctr*3+0], cy = base[ctr*3+1], cz = base[ctr*3+2];
    if (lane < 3) out_newxyz[gw*3 + lane] = base[ctr*3+lane];

    unsigned lt = (1u << lane) - 1u;
    int cnt = 0, first = 0;
    int* myidx = g_idx + (size_t)gw*KK;
    for (int j0 = 0; j0 < NN; j0 += 64) {
        int ja = j0 + lane, jb = j0 + 32 + lane;
        float dxa = base[ja*3+0]-cx, dya = base[ja*3+1]-cy, dza = base[ja*3+2]-cz;
        float dxb = base[jb*3+0]-cx, dyb = base[jb*3+1]-cy, dzb = base[jb*3+2]-cz;
        bool wa = (dxa*dxa + dya*dya + dza*dza) < R2;
        bool wb = (dxb*dxb + dyb*dyb + dzb*dzb) < R2;
        unsigned m1 = __ballot_sync(0xffffffffu, wa);
        unsigned m2 = __ballot_sync(0xffffffffu, wb);
        if (m1 | m2) {
            if (cnt == 0)
                first = m1 ? (j0 + __ffs(m1) - 1) : (j0 + 32 + __ffs(m2) - 1);
            int c1 = __popc(m1);
            int p1 = __popc(m1 & lt);
            if (wa && (cnt + p1) < KK) myidx[cnt + p1] = ja;
            int p2 = __popc(m2 & lt);
            if (wb && (cnt + c1 + p2) < KK) myidx[cnt + c1 + p2] = jb;
            cnt += c1 + __popc(m2);
            if (cnt >= KK) break;
        }
    }
    int ce = cnt < KK ? cnt : KK;
    if (lane >= ce) myidx[lane] = first;
}

// ---------------------------------------------------------------------------
// 3) weight split into per-segment smem image:
//    layout per col-tile: [chunk c][seg 0=hi,1=lo][n(128)][16 bf16]
//    perm=1 (layer1): k<128 -> w[:,3+k]; 128..130 -> w[:,k-128]; else 0
// ---------------------------------------------------------------------------
__global__ void splitw_kernel(const float* __restrict__ w,
                              unsigned char* __restrict__ out,
                              int Cin, int nSeg, int perm) {
    int o = blockIdx.x, k = threadIdx.x;
    int wt = o >> 7, n = o & 127;
    float v;
    if (perm) {
        if (k < 128)      v = w[o*Cin + 3 + k];
        else if (k < 131) v = w[o*Cin + (k - 128)];
        else              v = 0.f;
    } else {
        v = (k < Cin) ? w[o*Cin + k] : 0.f;
    }
    __nv_bfloat16 h = __float2bfloat16_rn(v);
    __nv_bfloat16 l = __float2bfloat16_rn(v - __bfloat162float(h));
    int c = k >> 4, kk = k & 15;
    unsigned char* base = out + (size_t)wt * nSeg * SEGB;
    *(__nv_bfloat16*)(base + ((size_t)(2*c+0)*128 + n)*32 + kk*2) = h;
    *(__nv_bfloat16*)(base + ((size_t)(2*c+1)*128 + n)*32 + kk*2) = l;
}

// ---------------------------------------------------------------------------
// Persistent fused GEMM, smem-staged A, 8 warps, software-pipelined operands.
//   MODE 0: A = virtual gathered X1 (featT + dxyz), K=144 (9 chunks) -> Y1
//   MODE 1: A = Y1, act=relu(bn).  K=128.                            -> Y2
//   MODE 2: A = Y2, act=relu(bn).  stats + K-group max, no Y.
// Block 128x128, 256 thr (8 warps: wm 0..3 x wn 0..1), warp tile 32x64.
// A rows cp.async-staged whole-K (coalesced, double-buffered across tiles).
// WITHIN a tile, chunk c+1's A-LDS and B-ldmatrix are issued BEFORE chunk c's
// split+MMA block (register double buffers) so smem latency hides under MMA.
// NO __syncthreads in the tile loop -- per-wm named barrier (2 warps, 64 thr).
// Split precision: A,W {hi,lo}; products hi*hi + hi*lo + lo*hi.
// ---------------------------------------------------------------------------
template<int MODE>
__global__ __launch_bounds__(256, 1)
void gemm_rr(const float* __restrict__ A,
             const unsigned char* __restrict__ Wt,
             const float* __restrict__ bias,
             const float* __restrict__ bn_a, const float* __restrict__ bn_c,
             float* __restrict__ Y,
             const float* __restrict__ xyz, const float* __restrict__ newxyz) {
    constexpr int NCH   = (MODE == 0) ? 9 : 8;
    constexpr int NSEG  = 2 * NCH;
    constexpr int COUTT = (MODE == 2) ? 256 : 128;

    extern __shared__ unsigned char dsm[];
    unsigned char* Wsm = dsm;                        // NSEG*SEGB
    float* smA = (float*)(dsm + NSEG*SEGB);          // 2 * STAGEF floats

    __shared__ float s_bias[128];
    __shared__ float s_bna[128], s_bnc[128];

    int tid  = threadIdx.x;
    int lane = tid & 31, warp = tid >> 5;
    int wm = warp >> 1, wn = warp & 1;
    int colTile = blockIdx.y * 128;
    int gg = lane >> 2, tq = lane & 3;

    uint32_t wsm_a = smem_u32(Wsm);

    if (tid < 128) {
        s_bias[tid] = bias[colTile + tid];
        if (MODE != 0) { s_bna[tid] = bn_a[tid]; s_bnc[tid] = bn_c[tid]; }
    }
    // W tile -> smem (once per CTA)
    {
        const unsigned char* wsrc = Wt + (size_t)blockIdx.y * NSEG * SEGB;
        for (int i = tid; i < NSEG*256; i += 256)
            CP_ASYNC16(wsm_a + i*16, wsrc + (size_t)i*16);
        CP_COMMIT();
    }

    // ---- A stage prefetch: this warp stages 16 of its pair's 32 rows,
    //      whole K (128 floats), one coalesced cp.async row per instruction
    uint32_t smA_a = smem_u32(smA);
    auto prefetch = [&](int t, int buf) {
        if (t < NBLK) {
            #pragma unroll
            for (int i = 0; i < 16; i++) {
                int r  = wn*16 + i;                  // row within group
                int rg = t*128 + wm*32 + r;
                const float* src;
                if (MODE == 0) {
                    int jj = g_idx[rg];
                    int bb = rg >> 15;
                    src = g_featT + ((size_t)bb*NN + jj)*CC;
                } else {
                    src = A + (size_t)rg*128;
                }
                uint32_t dst = smA_a +
                    (uint32_t)(((buf*4 + wm)*32 + r)*SROW + lane*4)*4;
                CP_ASYNC16(dst, src + lane*4);
            }
        }
        CP_COMMIT();
    };

    prefetch(blockIdx.x, 0);
    CP_WAIT0();
    __syncthreads();          // once: W + first stage visible to everyone

    uint32_t boff = (uint32_t)((wn*64 + (lane & 7) + ((lane >> 4) & 1)*8)*32
                               + ((lane >> 3) & 1)*16);
    int buf = 0;

    for (int t = blockIdx.x; t < NBLK; t += gridDim.x) {
        // prefetch next tile into the other buffer (overlaps this compute)
        prefetch(t + gridDim.x, buf ^ 1);

        // ---- per-tile dxyz (MODE 0 only, fragment-resident)
        float dxr[2][2], dyr[2][2], dzr[2][2];
        if (MODE == 0) {
            #pragma unroll
            for (int mf = 0; mf < 2; mf++)
                #pragma unroll
                for (int h = 0; h < 2; h++) {
                    int rg = t*128 + wm*32 + mf*16 + h*8 + gg;
                    int jj = g_idx[rg];
                    int bb = rg >> 15;
                    const float* pp = xyz    + ((size_t)bb*NN + jj)*3;
                    const float* cq = newxyz + (size_t)(rg >> 5)*3;
                    dxr[mf][h] = pp[0]-cq[0];
                    dyr[mf][h] = pp[1]-cq[1];
                    dzr[mf][h] = pp[2]-cq[2];
                }
        }

        // fragment-row base offsets in the stage (floats)
        const float* arow[2][2];
        #pragma unroll
        for (int mf = 0; mf < 2; mf++)
            #pragma unroll
            for (int h = 0; h < 2; h++)
                arow[mf][h] = smA + (size_t)(((buf*4 + wm)*32
                                    + mf*16 + h*8 + gg)*SROW + 2*tq);

        float acc[2][8][4];
        #pragma unroll
        for (int mf = 0; mf < 2; mf++)
            #pragma unroll
            for (int nf = 0; nf < 8; nf++)
                #pragma unroll
                for (int r2 = 0; r2 < 4; r2++) acc[mf][nf][r2] = 0.f;

        // ---- register double buffers for software pipelining ----
        float2   av0[2][4], av8[2][4];       // raw A: [parity][mf*2+h]
        uint32_t bh[2][8][2], bl[2][8][2];   // B frags: [parity][nf][]

        auto loadA = [&](int c, int p) {
            #pragma unroll
            for (int mf = 0; mf < 2; mf++)
                #pragma unroll
                for (int h = 0; h < 2; h++) {
                    av0[p][mf*2+h] = *(const float2*)(arow[mf][h] + c*16);
                    av8[p][mf*2+h] = *(const float2*)(arow[mf][h] + c*16 + 8);
                }
        };
        auto loadB = [&](int c, int p) {
            #pragma unroll
            for (int j = 0; j < 4; j++) {
                uint32_t r4[4];
                ldm_x4(r4, wsm_a + (uint32_t)(2*c)*SEGB + boff + j*512);
                bh[p][2*j][0] = r4[0]; bh[p][2*j][1] = r4[1];
                bh[p][2*j+1][0] = r4[2]; bh[p][2*j+1][1] = r4[3];
                ldm_x4(r4, wsm_a + (uint32_t)(2*c+1)*SEGB + boff + j*512);
                bl[p][2*j][0] = r4[0]; bl[p][2*j][1] = r4[1];
                bl[p][2*j+1][0] = r4[2]; bl[p][2*j+1][1] = r4[3];
            }
        };

        loadA(0, 0);
        loadB(0, 0);

        #pragma unroll
        for (int c = 0; c < NCH; c++) {
            int p = c & 1;
            // ---- issue next chunk's loads FIRST (hide under this MMA) ----
            if (c + 1 < NCH) {
                if (!(MODE == 0 && c + 1 == 8)) loadA(c + 1, p ^ 1);
                loadB(c + 1, p ^ 1);
            }

            // ---- build A fragments from the register buffer ----
            uint32_t ah[2][4], al[2][4];
            if (MODE == 0 && c == 8) {
                #pragma unroll
                for (int mf = 0; mf < 2; mf++) {
                    #pragma unroll
                    for (int h = 0; h < 2; h++) {
                        float2 v;   // cols 128+2tq, 129+2tq
                        v.x = (tq == 0) ? dxr[mf][h] : (tq == 1) ? dzr[mf][h] : 0.f;
                        v.y = (tq == 0) ? dyr[mf][h] : 0.f;
                        split2(v, ah[mf][h], al[mf][h]);
                    }
                    ah[mf][2] = 0u; al[mf][2] = 0u;   // cols >= 136: zero
                    ah[mf][3] = 0u; al[mf][3] = 0u;
                }
            } else {
                float2 ba0, bc0, ba8, bc8;
                if (MODE != 0) {
                    ba0 = *(const float2*)&s_bna[c*16 + 2*tq];
                    bc0 = *(const float2*)&s_bnc[c*16 + 2*tq];
                    ba8 = *(const float2*)&s_bna[c*16 + 2*tq + 8];
                    bc8 = *(const float2*)&s_bnc[c*16 + 2*tq + 8];
                }
                #pragma unroll
                for (int mf = 0; mf < 2; mf++)
                    #pragma unroll
                    for (int h = 0; h < 2; h++) {
                        float2 v0 = av0[p][mf*2+h];
                        float2 v8 = av8[p][mf*2+h];
                        if (MODE != 0) {
                            v0.x = fmaxf(fmaf(v0.x, ba0.x, bc0.x), 0.f);
                            v0.y = fmaxf(fmaf(v0.y, ba0.y, bc0.y), 0.f);
                            v8.x = fmaxf(fmaf(v8.x, ba8.x, bc8.x), 0.f);
                            v8.y = fmaxf(fmaf(v8.y, ba8.y, bc8.y), 0.f);
                        }
                        split2(v0, ah[mf][h],     al[mf][h]);      // reg h   (k0)
                        split2(v8, ah[mf][2 + h], al[mf][2 + h]);  // reg 2+h (k8)
                    }
            }

            // ---- MMAs on the CURRENT (already loaded) B fragments ----
            #pragma unroll
            for (int nf = 0; nf < 8; nf++) {
                mma16816(acc[0][nf], ah[0], bh[p][nf][0], bh[p][nf][1]);
                mma16816(acc[1][nf], ah[1], bh[p][nf][0], bh[p][nf][1]);
                mma16816(acc[0][nf], ah[0], bl[p][nf][0], bl[p][nf][1]);
                mma16816(acc[1][nf], ah[1], bl[p][nf][0], bl[p][nf][1]);
                mma16816(acc[0][nf], al[0], bh[p][nf][0], bh[p][nf][1]);
                mma16816(acc[1][nf], al[1], bh[p][nf][0], bh[p][nf][1]);
            }
        }

        // ---- epilogue: bias, Y write, per-warp stats/max (no barriers) ----
        float bs[8][2];
        #pragma unroll
        for (int nf = 0; nf < 8; nf++) {
            int col = wn*64 + nf*8 + 2*tq;
            bs[nf][0] = s_bias[col];
            bs[nf][1] = s_bias[col+1];
        }
        float s16[8][2], q16[8][2], m16[8][2];
        #pragma unroll
        for (int nf = 0; nf < 8; nf++)
            #pragma unroll
            for (int e = 0; e < 2; e++) { s16[nf][e]=0.f; q16[nf][e]=0.f; m16[nf][e]=-3.4e38f; }

        #pragma unroll
        for (int mf = 0; mf < 2; mf++) {
            #pragma unroll
            for (int nf = 0; nf < 8; nf++) {
                float v0 = acc[mf][nf][0] + bs[nf][0];
                float v1 = acc[mf][nf][1] + bs[nf][1];
                float v2 = acc[mf][nf][2] + bs[nf][0];
                float v3 = acc[mf][nf][3] + bs[nf][1];
                s16[nf][0] += v0 + v2;  s16[nf][1] += v1 + v3;
                q16[nf][0] = fmaf(v0,v0,fmaf(v2,v2,q16[nf][0]));
                q16[nf][1] = fmaf(v1,v1,fmaf(v3,v3,q16[nf][1]));
                m16[nf][0] = fmaxf(m16[nf][0], fmaxf(v0, v2));
                m16[nf][1] = fmaxf(m16[nf][1], fmaxf(v1, v3));
                if (MODE != 2) {
                    int r0 = t*128 + wm*32 + mf*16 + gg;
                    int cb = colTile + wn*64 + nf*8 + 2*tq;
                    *(float2*)(Y + (size_t)r0*COUTT + cb)     = make_float2(v0, v1);
                    *(float2*)(Y + (size_t)(r0+8)*COUTT + cb) = make_float2(v2, v3);
                }
            }
        }

        #pragma unroll
        for (int off = 4; off <= 16; off <<= 1) {
            #pragma unroll
            for (int nf = 0; nf < 8; nf++)
                #pragma unroll
                for (int e = 0; e < 2; e++) {
                    s16[nf][e] += __shfl_xor_sync(0xffffffffu, s16[nf][e], off);
                    q16[nf][e] += __shfl_xor_sync(0xffffffffu, q16[nf][e], off);
                    m16[nf][e] = fmaxf(m16[nf][e], __shfl_xor_sync(0xffffffffu, m16[nf][e], off));
                }
        }
        if (gg == 0) {
            size_t pb = (size_t)(t*4 + wm) * (2*COUTT);
            #pragma unroll
            for (int nf = 0; nf < 8; nf++)
                #pragma unroll
                for (int e = 0; e < 2; e++) {
                    int cl = wn*64 + nf*8 + 2*tq + e;
                    g_part[pb + colTile + cl]         = s16[nf][e];
                    g_part[pb + COUTT + colTile + cl] = q16[nf][e];
                    if (MODE == 2)
                        g_gmax[((size_t)(t*4 + wm))*COUT3 + colTile + cl] = m16[nf][e];
                }
        }

        // ---- stage t+1 arrived (mine) + pair sibling done with this buffer
        CP_WAIT0();
        BAR_PAIR(wm + 1);
        buf ^= 1;
    }
}

// ---------------------------------------------------------------------------
// BN finalize: fixed-order reduce over 4*NBLK per-warp partials
// ---------------------------------------------------------------------------
__global__ void bn_finalize_kernel(int C,
                                   const float* __restrict__ g,
                                   const float* __restrict__ beta,
                                   float* __restrict__ bn_a,
                                   float* __restrict__ bn_c) {
    __shared__ float sh_s[256], sh_q[256];
    int ch = blockIdx.x;
    int t  = threadIdx.x;
    float s = 0.f, q = 0.f;
    for (int b = t; b < 4*NBLK; b += 256) {
        size_t base = (size_t)b * (2*C);
        s += g_part[base + ch];
        q += g_part[base + C + ch];
    }
    sh_s[t] = s; sh_q[t] = q;
    __syncthreads();
    for (int off = 128; off > 0; off >>= 1) {
        if (t < off) { sh_s[t] += sh_s[t+off]; sh_q[t] += sh_q[t+off]; }
        __syncthreads();
    }
    if (t == 0) {
        const float invR = 1.0f / (float)RROWS;
        float mu  = sh_s[0] * invR;
        float var = sh_q[0] * invR - mu*mu;
        float a = g[ch] * rsqrtf(var + 1e-5f);
        bn_a[ch] = a;
        bn_c[ch] = beta[ch] - a*mu;
    }
}

// ---------------------------------------------------------------------------
// Final: relu(a3*gmax + c3) -> out (a3>0 so BN+relu commute with max)
// ---------------------------------------------------------------------------
__global__ void final_out_kernel(const float* __restrict__ bn_a,
                                 const float* __restrict__ bn_c,
                                 float* __restrict__ out) {
    int grp = blockIdx.x;
    int co  = threadIdx.x;
    float v = g_gmax[(size_t)grp*COUT3 + co];
    float r = fmaxf(fmaf(bn_a[co], v, bn_c[co]), 0.f);
    int b = grp >> 10, m = grp & 1023;
    out[OUT_XYZ_ELEMS + ((size_t)(b*COUT3 + co))*MM + m] = r;
}

// ---------------------------------------------------------------------------
// host launcher (gemm_rr<0> stays at launch index 3 for the ncu window)
// ---------------------------------------------------------------------------
extern "C" void kernel_launch(void* const* d_in, const int* in_sizes, int n_in,
                              void* d_out, int out_size) {
    const float* xyz     = (const float*)d_in[0];
    const float* feat    = (const float*)d_in[1];
    const int*   indices = (const int*)  d_in[2];
    const float* w1 = (const float*)d_in[3];
    const float* b1 = (const float*)d_in[4];
    const float* g1 = (const float*)d_in[5];
    const float* e1 = (const float*)d_in[6];
    const float* w2 = (const float*)d_in[7];
    const float* b2 = (const float*)d_in[8];
    const float* g2 = (const float*)d_in[9];
    const float* e2 = (const float*)d_in[10];
    const float* w3 = (const float*)d_in[11];
    const float* b3 = (const float*)d_in[12];
    const float* g3 = (const float*)d_in[13];
    const float* e3 = (const float*)d_in[14];
    float* out = (float*)d_out;

    float *Y1, *Y2, *bn;
    unsigned char *w1s, *w2s, *w3s;
    cudaGetSymbolAddress((void**)&Y1,  g_Y1);
    cudaGetSymbolAddress((void**)&Y2,  g_Y2);
    cudaGetSymbolAddress((void**)&bn,  g_bn);
    cudaGetSymbolAddress((void**)&w1s, g_w1s);
    cudaGetSymbolAddress((void**)&w2s, g_w2s);
    cudaGetSymbolAddress((void**)&w3s, g_w3s);
    float* a1 = bn;            float* c1 = bn + COUT3;
    float* a2 = bn + 2*COUT3;  float* c2 = bn + 3*COUT3;
    float* a3 = bn + 4*COUT3;  float* c3 = bn + 5*COUT3;

    int stageB = 2 * STAGEF * 4;              // 139264
    int smem1  = 18*SEGB + stageB;            // 212992
    int smem23 = 16*SEGB + stageB;            // 204800
    cudaFuncSetAttribute(gemm_rr<0>, cudaFuncAttributeMaxDynamicSharedMemorySize, smem1);
    cudaFuncSetAttribute(gemm_rr<1>, cudaFuncAttributeMaxDynamicSharedMemorySize, smem23);
    cudaFuncSetAttribute(gemm_rr<2>, cudaFuncAttributeMaxDynamicSharedMemorySize, smem23);

    // index 0..2: prep needed by gemm0
    splitw_kernel<<<COUT1, 144>>>(w1, w1s, 131, 18, 1);                     // 0
    {
        dim3 blk(32, 8);
        dim3 grd(NN/128, CC/32, BB);
        transpose_feat_kernel<<<grd, blk>>>(feat);                          // 1
    }
    ballquery_kernel<<<(BB*MM*32)/256, 256>>>(xyz, indices, out);           // 2

    // index 3: layer 1 GEMM (profiling target)
    gemm_rr<0><<<dim3(148,1), 256, smem1>>>(nullptr, w1s, b1, nullptr, nullptr,
                                            Y1, xyz, out);                  // 3
    bn_finalize_kernel<<<COUT1, 256>>>(COUT1, g1, e1, a1, c1);              // 4

    splitw_kernel<<<COUT2, 128>>>(w2, w2s, 128, 16, 0);                     // 5
    gemm_rr<1><<<dim3(148,1), 256, smem23>>>(Y1, w2s, b2, a1, c1,
                                             Y2, nullptr, nullptr);         // 6
    bn_finalize_kernel<<<COUT2, 256>>>(COUT2, g2, e2, a2, c2);              // 7

    splitw_kernel<<<COUT3, 128>>>(w3, w3s, 128, 16, 0);                     // 8
    gemm_rr<2><<<dim3(74,2), 256, smem23>>>(Y2, w3s, b3, a2, c2,
                                            nullptr, nullptr, nullptr);     // 9
    bn_finalize_kernel<<<COUT3, 256>>>(COUT3, g3, e3, a3, c3);              // 10

    final_out_kernel<<<NGRP, COUT3>>>(a3, c3, out);                         // 11
}